// round 15
// baseline (speedup 1.0000x reference)
#include <cuda_runtime.h>
#include <cstdint>

#define BB 8
#define LL 2048
#define DD 64
#define TQ 64
#define TK 64
#define NSPLIT 2

// index lists for mask compaction (device globals: allocation-free scratch)
__device__ int g_qlist[BB][LL];
__device__ int g_klist[BB][LL];
__device__ int g_qcnt[BB];
__device__ int g_kcnt[BB];

// split-K partial buffers (unnormalized O and row sums), indexed by compacted q
__device__ float g_Opart[NSPLIT][BB][LL][DD];   // ~16.8 MB static scratch
__device__ float g_rspart[NSPLIT][BB][LL];

// ---------------------------------------------------------------------------
// Kernel 1: deterministic per-batch compaction of valid q/k indices.
// ---------------------------------------------------------------------------
__global__ void compact_kernel(const int* __restrict__ qm, const int* __restrict__ km) {
    int b = blockIdx.x;
    int tid = threadIdx.x;
    __shared__ int cnt[256];

    // ---- q mask ----
    {
        const int* m = qm + (size_t)b * LL;
        int base = tid * 8;
        int c = 0;
#pragma unroll
        for (int k = 0; k < 8; ++k) c += (m[base + k] != 0);
        cnt[tid] = c;
        __syncthreads();
        if (tid == 0) {
            int run = 0;
            for (int t = 0; t < 256; ++t) { int v = cnt[t]; cnt[t] = run; run += v; }
            g_qcnt[b] = run;
        }
        __syncthreads();
        int pos = cnt[tid];
#pragma unroll
        for (int k = 0; k < 8; ++k)
            if (m[base + k] != 0) g_qlist[b][pos++] = base + k;
        __syncthreads();
    }
    // ---- k mask ----
    {
        const int* m = km + (size_t)b * LL;
        int base = tid * 8;
        int c = 0;
#pragma unroll
        for (int k = 0; k < 8; ++k) c += (m[base + k] != 0);
        cnt[tid] = c;
        __syncthreads();
        if (tid == 0) {
            int run = 0;
            for (int t = 0; t < 256; ++t) { int v = cnt[t]; cnt[t] = run; run += v; }
            g_kcnt[b] = run;
        }
        __syncthreads();
        int pos = cnt[tid];
#pragma unroll
        for (int k = 0; k < 8; ++k)
            if (m[base + k] != 0) g_klist[b][pos++] = base + k;
    }
}

// ---------------------------------------------------------------------------
// Kernel 2: fused attention over compacted indices, split-K over k tiles.
// 256 threads (16 tx x 16 ty), 4x4 micro-tiles, TQ=TK=64.
// blockIdx.z = split id; each split covers half the k tiles and emits
// unnormalized partial O rows + partial row sums (deterministic fixed split).
// Swizzle: element (row, float4-group g) at row*64 + ((g ^ (row>>2)) & 15)*4.
// All LDS/STS patterns conflict-free per 8-lane phase (K: g^tx distinct,
// V: tx^kg distinct, P store: tx^ty distinct, Q loads broadcast).
// __launch_bounds__(256,2): regs capped at 128 -> 2 CTAs/SM possible,
// smem 64KB x 2 = 128KB <= 228KB carveout.
// ---------------------------------------------------------------------------
__device__ __forceinline__ int swz(int row, int g) {
    return row * 64 + (((g ^ (row >> 2)) & 15) << 2);
}

extern __shared__ float smem[];

__global__ void __launch_bounds__(256, 2)
attn_kernel(const float* __restrict__ Q, const float* __restrict__ K,
            const float* __restrict__ V) {
    int b  = blockIdx.y;
    int sp = blockIdx.z;
    int nq = g_qcnt[b];
    int nk = g_kcnt[b];
    int q0 = blockIdx.x * TQ;
    if (q0 >= nq) return;   // early exit before any barrier

    float* Qs = smem;            // 4096 floats
    float* Ks = smem + 4096;     // 4096
    float* Vs = smem + 8192;     // 4096
    float* Ps = smem + 12288;    // 4096

    int tid = threadIdx.x;
    int tx = tid & 15;           // k / d micro-tile column group
    int ty = tid >> 4;           // q micro-tile row group

    // ---- load Q tile (gathered, pre-scaled by 1/sqrt(D)=0.125) ----
    {
        int g = tid & 15;
        int r = tid >> 4;
#pragma unroll
        for (int pass = 0; pass < 4; ++pass) {
            int row = r + pass * 16;
            int qi = q0 + row;
            float4 v = make_float4(0.f, 0.f, 0.f, 0.f);
            if (qi < nq) {
                int src = g_qlist[b][qi];
                v = *(const float4*)&Q[((size_t)b * LL + src) * DD + g * 4];
                v.x *= 0.125f; v.y *= 0.125f; v.z *= 0.125f; v.w *= 0.125f;
            }
            *(float4*)&Qs[swz(row, g)] = v;
        }
    }
    __syncthreads();

    float acc[4][4];   // O accumulator: q rows ty*4+i, d cols tx*4+j
    float rs[4];       // partial row sums over this thread's k columns
#pragma unroll
    for (int i = 0; i < 4; ++i) {
        rs[i] = 0.f;
#pragma unroll
        for (int j = 0; j < 4; ++j) acc[i][j] = 0.f;
    }

    int ntiles = (nk + TK - 1) / TK;
    int half   = (ntiles + 1) >> 1;
    int tbeg   = sp * half;
    int tend   = (sp == 0) ? half : ntiles;
    if (tend > ntiles) tend = ntiles;

    for (int t = tbeg; t < tend; ++t) {
        int k0 = t * TK;

        // ---- load K and V tiles (gathered) ----
        {
            int g = tid & 15;
            int r = tid >> 4;
#pragma unroll
            for (int pass = 0; pass < 4; ++pass) {
                int row = r + pass * 16;
                int ki = k0 + row;
                float4 kv = make_float4(0.f, 0.f, 0.f, 0.f);
                float4 vv = make_float4(0.f, 0.f, 0.f, 0.f);
                if (ki < nk) {
                    int src = g_klist[b][ki];
                    const float* kp = &K[((size_t)b * LL + src) * DD + g * 4];
                    const float* vp = &V[((size_t)b * LL + src) * DD + g * 4];
                    kv = *(const float4*)kp;
                    vv = *(const float4*)vp;
                }
                *(float4*)&Ks[swz(row, g)] = kv;
                *(float4*)&Vs[swz(row, g)] = vv;
            }
        }
        __syncthreads();

        // ---- phase A: S = Qs @ Ks^T (4x4 micro-tile) ----
        float s[4][4];
#pragma unroll
        for (int i = 0; i < 4; ++i)
#pragma unroll
            for (int j = 0; j < 4; ++j) s[i][j] = 0.f;

#pragma unroll
        for (int dg = 0; dg < 16; ++dg) {
            float4 qv[4], kv[4];
#pragma unroll
            for (int i = 0; i < 4; ++i) qv[i] = *(float4*)&Qs[swz(ty * 4 + i, dg)];
#pragma unroll
            for (int j = 0; j < 4; ++j) kv[j] = *(float4*)&Ks[swz(tx * 4 + j, dg)];
#pragma unroll
            for (int i = 0; i < 4; ++i)
#pragma unroll
                for (int j = 0; j < 4; ++j)
                    s[i][j] += qv[i].x * kv[j].x + qv[i].y * kv[j].y +
                               qv[i].z * kv[j].z + qv[i].w * kv[j].w;
        }

        // exp (compacted k all valid; only tile-padding columns masked),
        // accumulate row sums, write P tile
#pragma unroll
        for (int i = 0; i < 4; ++i) {
            float pv[4];
#pragma unroll
            for (int j = 0; j < 4; ++j) {
                int kc = k0 + tx * 4 + j;
                float e = (kc < nk) ? __expf(s[i][j]) : 0.0f;
                pv[j] = e;
                rs[i] += e;
            }
            *(float4*)&Ps[swz(ty * 4 + i, tx)] =
                make_float4(pv[0], pv[1], pv[2], pv[3]);
        }
        __syncthreads();

        // ---- phase B: O += P @ V (4x4 micro-tile over q x d) ----
#pragma unroll
        for (int kg = 0; kg < 16; ++kg) {
            float4 p[4];
#pragma unroll
            for (int i = 0; i < 4; ++i) p[i] = *(float4*)&Ps[swz(ty * 4 + i, kg)];
            float4 v0 = *(float4*)&Vs[swz(kg * 4 + 0, tx)];
            float4 v1 = *(float4*)&Vs[swz(kg * 4 + 1, tx)];
            float4 v2 = *(float4*)&Vs[swz(kg * 4 + 2, tx)];
            float4 v3 = *(float4*)&Vs[swz(kg * 4 + 3, tx)];
#pragma unroll
            for (int i = 0; i < 4; ++i) {
                acc[i][0] += p[i].x * v0.x + p[i].y * v1.x + p[i].z * v2.x + p[i].w * v3.x;
                acc[i][1] += p[i].x * v0.y + p[i].y * v1.y + p[i].z * v2.y + p[i].w * v3.y;
                acc[i][2] += p[i].x * v0.z + p[i].y * v1.z + p[i].z * v2.z + p[i].w * v3.z;
                acc[i][3] += p[i].x * v0.w + p[i].y * v1.w + p[i].z * v2.w + p[i].w * v3.w;
            }
        }
        __syncthreads();
    }

    // ---- reduce row sums across the 16 tx threads (deterministic order) ----
    float* RS = Ks;   // reuse: [qr][tx] partials, 64*16 floats
#pragma unroll
    for (int i = 0; i < 4; ++i)
        RS[(ty * 4 + i) * 16 + tx] = rs[i];
    __syncthreads();

    if (tid < 64) {
        int qi = q0 + tid;
        if (qi < nq) {
            float tsum = 0.f;
#pragma unroll
            for (int u = 0; u < 16; ++u) tsum += RS[tid * 16 + u];
            g_rspart[sp][b][qi] = tsum;   // NOT clamped; clamp happens in combine
        }
    }

    // ---- write unnormalized O partials at compacted positions ----
#pragma unroll
    for (int i = 0; i < 4; ++i) {
        int qi = q0 + ty * 4 + i;
        if (qi < nq) {
            *(float4*)&g_Opart[sp][b][qi][tx * 4] =
                make_float4(acc[i][0], acc[i][1], acc[i][2], acc[i][3]);
        }
    }
}

// ---------------------------------------------------------------------------
// Kernel 3: combine splits, clamp rowsum, normalize, scatter to output.
// 256 threads = 4 q rows x 64 d. Grid (LL/4, BB).
// ---------------------------------------------------------------------------
__global__ void combine_kernel(float* __restrict__ out) {
    int b  = blockIdx.y;
    int nq = g_qcnt[b];
    int qi = blockIdx.x * 4 + (threadIdx.x >> 6);
    int d  = threadIdx.x & 63;
    if (qi >= nq) return;
    float rs = fmaxf(g_rspart[0][b][qi] + g_rspart[1][b][qi], 1.0f);
    float o  = (g_Opart[0][b][qi][d] + g_Opart[1][b][qi][d]) / rs;
    int src  = g_qlist[b][qi];
    out[((size_t)b * LL + src) * DD + d] = o;
}

// ---------------------------------------------------------------------------
extern "C" void kernel_launch(void* const* d_in, const int* in_sizes, int n_in,
                              void* d_out, int out_size) {
    const float* Q  = (const float*)d_in[0];
    const float* K  = (const float*)d_in[1];
    const float* V  = (const float*)d_in[2];
    const int*   qm = (const int*)d_in[3];
    const int*   km = (const int*)d_in[4];
    float* out = (float*)d_out;

    // 64 KB dynamic smem (> 48 KB default) — idempotent host-side config
    cudaFuncSetAttribute(attn_kernel,
                         cudaFuncAttributeMaxDynamicSharedMemorySize, 65536);

    // zero-fill output: invalid q rows stay exactly 0
    cudaMemsetAsync(out, 0, (size_t)out_size * sizeof(float));

    compact_kernel<<<BB, 256>>>(qm, km);

    dim3 grid(LL / TQ, BB, NSPLIT);   // 32 x 8 x 2; ~half exit early (q compaction)
    attn_kernel<<<grid, 256, 65536>>>(Q, K, V);

    dim3 cgrid(LL / 4, BB);
    combine_kernel<<<cgrid, 256>>>(out);
}

// round 16
// speedup vs baseline: 1.0026x; 1.0026x over previous
#include <cuda_runtime.h>
#include <cstdint>

#define BB 8
#define LL 2048
#define DD 64
#define TQ 64
#define TK 64
#define NSPLIT 2

// index lists for mask compaction (device globals: allocation-free scratch)
__device__ int g_qlist[BB][LL];
__device__ int g_klist[BB][LL];
__device__ int g_qcnt[BB];
__device__ int g_kcnt[BB];

// split-K partial buffers (unnormalized O and row sums), indexed by compacted q
__device__ float g_Opart[NSPLIT][BB][LL][DD];   // ~16.8 MB static scratch
__device__ float g_rspart[NSPLIT][BB][LL];

// ---------------------------------------------------------------------------
// Kernel 1: deterministic per-batch compaction of valid q/k indices.
// ---------------------------------------------------------------------------
__global__ void compact_kernel(const int* __restrict__ qm, const int* __restrict__ km) {
    int b = blockIdx.x;
    int tid = threadIdx.x;
    __shared__ int cnt[256];

    // ---- q mask ----
    {
        const int* m = qm + (size_t)b * LL;
        int base = tid * 8;
        int c = 0;
#pragma unroll
        for (int k = 0; k < 8; ++k) c += (m[base + k] != 0);
        cnt[tid] = c;
        __syncthreads();
        if (tid == 0) {
            int run = 0;
            for (int t = 0; t < 256; ++t) { int v = cnt[t]; cnt[t] = run; run += v; }
            g_qcnt[b] = run;
        }
        __syncthreads();
        int pos = cnt[tid];
#pragma unroll
        for (int k = 0; k < 8; ++k)
            if (m[base + k] != 0) g_qlist[b][pos++] = base + k;
        __syncthreads();
    }
    // ---- k mask ----
    {
        const int* m = km + (size_t)b * LL;
        int base = tid * 8;
        int c = 0;
#pragma unroll
        for (int k = 0; k < 8; ++k) c += (m[base + k] != 0);
        cnt[tid] = c;
        __syncthreads();
        if (tid == 0) {
            int run = 0;
            for (int t = 0; t < 256; ++t) { int v = cnt[t]; cnt[t] = run; run += v; }
            g_kcnt[b] = run;
        }
        __syncthreads();
        int pos = cnt[tid];
#pragma unroll
        for (int k = 0; k < 8; ++k)
            if (m[base + k] != 0) g_klist[b][pos++] = base + k;
    }
}

// ---------------------------------------------------------------------------
// Kernel 2: fused attention over compacted indices, split-K over k tiles.
// 256 threads (16 tx x 16 ty), 4x4 micro-tiles, TQ=TK=64.
// blockIdx.z = split id; each split covers half the k tiles and emits
// unnormalized partial O rows + partial row sums (deterministic fixed split).
// Swizzle: element (row, float4-group g) at row*64 + ((g ^ (row>>2)) & 15)*4.
// All LDS/STS patterns conflict-free per 8-lane phase (K: g^tx distinct,
// V: tx^kg distinct, P store: tx^ty distinct, Q loads broadcast).
// __launch_bounds__(256,2): regs capped at 128 -> 2 CTAs/SM possible,
// smem 64KB x 2 = 128KB <= 228KB carveout.
// ---------------------------------------------------------------------------
__device__ __forceinline__ int swz(int row, int g) {
    return row * 64 + (((g ^ (row >> 2)) & 15) << 2);
}

extern __shared__ float smem[];

__global__ void __launch_bounds__(256, 2)
attn_kernel(const float* __restrict__ Q, const float* __restrict__ K,
            const float* __restrict__ V) {
    int b  = blockIdx.y;
    int sp = blockIdx.z;
    int nq = g_qcnt[b];
    int nk = g_kcnt[b];
    int q0 = blockIdx.x * TQ;
    if (q0 >= nq) return;   // early exit before any barrier

    float* Qs = smem;            // 4096 floats
    float* Ks = smem + 4096;     // 4096
    float* Vs = smem + 8192;     // 4096
    float* Ps = smem + 12288;    // 4096

    int tid = threadIdx.x;
    int tx = tid & 15;           // k / d micro-tile column group
    int ty = tid >> 4;           // q micro-tile row group

    // ---- load Q tile (gathered, pre-scaled by 1/sqrt(D)=0.125) ----
    {
        int g = tid & 15;
        int r = tid >> 4;
#pragma unroll
        for (int pass = 0; pass < 4; ++pass) {
            int row = r + pass * 16;
            int qi = q0 + row;
            float4 v = make_float4(0.f, 0.f, 0.f, 0.f);
            if (qi < nq) {
                int src = g_qlist[b][qi];
                v = *(const float4*)&Q[((size_t)b * LL + src) * DD + g * 4];
                v.x *= 0.125f; v.y *= 0.125f; v.z *= 0.125f; v.w *= 0.125f;
            }
            *(float4*)&Qs[swz(row, g)] = v;
        }
    }
    __syncthreads();

    float acc[4][4];   // O accumulator: q rows ty*4+i, d cols tx*4+j
    float rs[4];       // partial row sums over this thread's k columns
#pragma unroll
    for (int i = 0; i < 4; ++i) {
        rs[i] = 0.f;
#pragma unroll
        for (int j = 0; j < 4; ++j) acc[i][j] = 0.f;
    }

    int ntiles = (nk + TK - 1) / TK;
    int half   = (ntiles + 1) >> 1;
    int tbeg   = sp * half;
    int tend   = (sp == 0) ? half : ntiles;
    if (tend > ntiles) tend = ntiles;

    for (int t = tbeg; t < tend; ++t) {
        int k0 = t * TK;

        // ---- load K and V tiles (gathered) ----
        {
            int g = tid & 15;
            int r = tid >> 4;
#pragma unroll
            for (int pass = 0; pass < 4; ++pass) {
                int row = r + pass * 16;
                int ki = k0 + row;
                float4 kv = make_float4(0.f, 0.f, 0.f, 0.f);
                float4 vv = make_float4(0.f, 0.f, 0.f, 0.f);
                if (ki < nk) {
                    int src = g_klist[b][ki];
                    const float* kp = &K[((size_t)b * LL + src) * DD + g * 4];
                    const float* vp = &V[((size_t)b * LL + src) * DD + g * 4];
                    kv = *(const float4*)kp;
                    vv = *(const float4*)vp;
                }
                *(float4*)&Ks[swz(row, g)] = kv;
                *(float4*)&Vs[swz(row, g)] = vv;
            }
        }
        __syncthreads();

        // ---- phase A: S = Qs @ Ks^T (4x4 micro-tile) ----
        float s[4][4];
#pragma unroll
        for (int i = 0; i < 4; ++i)
#pragma unroll
            for (int j = 0; j < 4; ++j) s[i][j] = 0.f;

#pragma unroll
        for (int dg = 0; dg < 16; ++dg) {
            float4 qv[4], kv[4];
#pragma unroll
            for (int i = 0; i < 4; ++i) qv[i] = *(float4*)&Qs[swz(ty * 4 + i, dg)];
#pragma unroll
            for (int j = 0; j < 4; ++j) kv[j] = *(float4*)&Ks[swz(tx * 4 + j, dg)];
#pragma unroll
            for (int i = 0; i < 4; ++i)
#pragma unroll
                for (int j = 0; j < 4; ++j)
                    s[i][j] += qv[i].x * kv[j].x + qv[i].y * kv[j].y +
                               qv[i].z * kv[j].z + qv[i].w * kv[j].w;
        }

        // exp (compacted k all valid; only tile-padding columns masked),
        // accumulate row sums, write P tile
#pragma unroll
        for (int i = 0; i < 4; ++i) {
            float pv[4];
#pragma unroll
            for (int j = 0; j < 4; ++j) {
                int kc = k0 + tx * 4 + j;
                float e = (kc < nk) ? __expf(s[i][j]) : 0.0f;
                pv[j] = e;
                rs[i] += e;
            }
            *(float4*)&Ps[swz(ty * 4 + i, tx)] =
                make_float4(pv[0], pv[1], pv[2], pv[3]);
        }
        __syncthreads();

        // ---- phase B: O += P @ V (4x4 micro-tile over q x d) ----
#pragma unroll
        for (int kg = 0; kg < 16; ++kg) {
            float4 p[4];
#pragma unroll
            for (int i = 0; i < 4; ++i) p[i] = *(float4*)&Ps[swz(ty * 4 + i, kg)];
            float4 v0 = *(float4*)&Vs[swz(kg * 4 + 0, tx)];
            float4 v1 = *(float4*)&Vs[swz(kg * 4 + 1, tx)];
            float4 v2 = *(float4*)&Vs[swz(kg * 4 + 2, tx)];
            float4 v3 = *(float4*)&Vs[swz(kg * 4 + 3, tx)];
#pragma unroll
            for (int i = 0; i < 4; ++i) {
                acc[i][0] += p[i].x * v0.x + p[i].y * v1.x + p[i].z * v2.x + p[i].w * v3.x;
                acc[i][1] += p[i].x * v0.y + p[i].y * v1.y + p[i].z * v2.y + p[i].w * v3.y;
                acc[i][2] += p[i].x * v0.z + p[i].y * v1.z + p[i].z * v2.z + p[i].w * v3.z;
                acc[i][3] += p[i].x * v0.w + p[i].y * v1.w + p[i].z * v2.w + p[i].w * v3.w;
            }
        }
        __syncthreads();
    }

    // ---- reduce row sums across the 16 tx threads (deterministic order) ----
    float* RS = Ks;   // reuse: [qr][tx] partials, 64*16 floats
#pragma unroll
    for (int i = 0; i < 4; ++i)
        RS[(ty * 4 + i) * 16 + tx] = rs[i];
    __syncthreads();

    if (tid < 64) {
        int qi = q0 + tid;
        if (qi < nq) {
            float tsum = 0.f;
#pragma unroll
            for (int u = 0; u < 16; ++u) tsum += RS[tid * 16 + u];
            g_rspart[sp][b][qi] = tsum;   // NOT clamped; clamp happens in combine
        }
    }

    // ---- write unnormalized O partials at compacted positions ----
#pragma unroll
    for (int i = 0; i < 4; ++i) {
        int qi = q0 + ty * 4 + i;
        if (qi < nq) {
            *(float4*)&g_Opart[sp][b][qi][tx * 4] =
                make_float4(acc[i][0], acc[i][1], acc[i][2], acc[i][3]);
        }
    }
}

// ---------------------------------------------------------------------------
// Kernel 3: combine splits, clamp rowsum, normalize, scatter to output.
// 256 threads = 4 q rows x 64 d. Grid (LL/4, BB).
// ---------------------------------------------------------------------------
__global__ void combine_kernel(float* __restrict__ out) {
    int b  = blockIdx.y;
    int nq = g_qcnt[b];
    int qi = blockIdx.x * 4 + (threadIdx.x >> 6);
    int d  = threadIdx.x & 63;
    if (qi >= nq) return;
    float rs = fmaxf(g_rspart[0][b][qi] + g_rspart[1][b][qi], 1.0f);
    float o  = (g_Opart[0][b][qi][d] + g_Opart[1][b][qi][d]) / rs;
    int src  = g_qlist[b][qi];
    out[((size_t)b * LL + src) * DD + d] = o;
}

// ---------------------------------------------------------------------------
extern "C" void kernel_launch(void* const* d_in, const int* in_sizes, int n_in,
                              void* d_out, int out_size) {
    const float* Q  = (const float*)d_in[0];
    const float* K  = (const float*)d_in[1];
    const float* V  = (const float*)d_in[2];
    const int*   qm = (const int*)d_in[3];
    const int*   km = (const int*)d_in[4];
    float* out = (float*)d_out;

    // 64 KB dynamic smem (> 48 KB default) — idempotent host-side config
    cudaFuncSetAttribute(attn_kernel,
                         cudaFuncAttributeMaxDynamicSharedMemorySize, 65536);

    // zero-fill output: invalid q rows stay exactly 0
    cudaMemsetAsync(out, 0, (size_t)out_size * sizeof(float));

    compact_kernel<<<BB, 256>>>(qm, km);

    dim3 grid(LL / TQ, BB, NSPLIT);   // 32 x 8 x 2; ~half exit early (q compaction)
    attn_kernel<<<grid, 256, 65536>>>(Q, K, V);

    dim3 cgrid(LL / 4, BB);
    combine_kernel<<<cgrid, 256>>>(out);
}

// round 17
// speedup vs baseline: 1.1732x; 1.1701x over previous
#include <cuda_runtime.h>
#include <cstdint>

#define BB 8
#define LL 2048
#define DD 64
#define TQ 64
#define TK 64
#define NSPLIT 2

// index lists for mask compaction (device globals: allocation-free scratch)
__device__ int g_qlist[BB][LL];
__device__ int g_klist[BB][LL];
__device__ int g_qcnt[BB];
__device__ int g_kcnt[BB];

// split-K partial buffers (unnormalized O and row sums), indexed by compacted q
__device__ float g_Opart[NSPLIT][BB][LL][DD];
__device__ float g_rspart[NSPLIT][BB][LL];

// ---------------------------------------------------------------------------
// packed fp32x2 helpers (Blackwell FFMA2 — only reachable via PTX)
// ---------------------------------------------------------------------------
__device__ __forceinline__ unsigned long long pack2(float a, float b) {
    unsigned long long r;
    asm("mov.b64 %0, {%1, %2};" : "=l"(r) : "f"(a), "f"(b));
    return r;
}
__device__ __forceinline__ void unpack2(unsigned long long v, float& a, float& b) {
    asm("mov.b64 {%0, %1}, %2;" : "=f"(a), "=f"(b) : "l"(v));
}
__device__ __forceinline__ void ffma2(unsigned long long& d,
                                      unsigned long long a, unsigned long long b) {
    asm("fma.rn.f32x2 %0, %1, %2, %0;" : "+l"(d) : "l"(a), "l"(b));
}

// ---------------------------------------------------------------------------
// Kernel 1: deterministic per-batch compaction (shfl warp scan, no serial loop)
// ---------------------------------------------------------------------------
__device__ __forceinline__ void compact_one(const int* __restrict__ m,
                                            int* __restrict__ list,
                                            int* __restrict__ cntp,
                                            int tid, int* wsum) {
    int lane = tid & 31, wid = tid >> 5;
    int base = tid * 8;
    int c = 0;
#pragma unroll
    for (int k = 0; k < 8; ++k) c += (m[base + k] != 0);
    // inclusive warp scan of c
    int sc = c;
#pragma unroll
    for (int o = 1; o < 32; o <<= 1) {
        int v = __shfl_up_sync(0xFFFFFFFFu, sc, o);
        if (lane >= o) sc += v;
    }
    if (lane == 31) wsum[wid] = sc;
    __syncthreads();
    if (tid == 0) {
        int run = 0;
#pragma unroll
        for (int w = 0; w < 8; ++w) { int v = wsum[w]; wsum[w] = run; run += v; }
        *cntp = run;
    }
    __syncthreads();
    int pos = wsum[wid] + sc - c;   // exclusive prefix for this thread
#pragma unroll
    for (int k = 0; k < 8; ++k)
        if (m[base + k] != 0) list[pos++] = base + k;
    __syncthreads();
}

__global__ void compact_kernel(const int* __restrict__ qm, const int* __restrict__ km) {
    int b = blockIdx.x;
    int tid = threadIdx.x;
    __shared__ int wsum[8];
    compact_one(qm + (size_t)b * LL, g_qlist[b], &g_qcnt[b], tid, wsum);
    compact_one(km + (size_t)b * LL, g_klist[b], &g_kcnt[b], tid, wsum);
}

// ---------------------------------------------------------------------------
// Kernel 2: fused attention, split-K, FFMA2 math.
// 256 threads (16 tx x 16 ty), 4x4 micro-tiles, TQ=TK=64.
// Smem:
//   Qs [q][d]  element (q,d)  at swz(q, d>>2) + (d&3)
//   Kt [d][k]  element (d,k)  at swz(d, k>>2) + (k&3)   (TRANSPOSED)
//   Vs [k][d]  element (k,d)  at swz(k, d>>2) + (d&3)
//   Ps [q][k]  element (q,k)  at swz(q, k>>2) + (k&3)
// swz(row,g) = row*64 + ((g ^ (row>>2)) & 15)*4  -> all patterns conflict-free.
// Phase A: s-pairs over k, K pairs loaded as ulonglong2, Q broadcast-packed.
// Phase B: acc-pairs over d, V pairs loaded as ulonglong2, P broadcast-packed.
// __launch_bounds__(256,2): 2 CTAs/SM (128 regs), smem 2x64KB = 128KB.
// ---------------------------------------------------------------------------
__device__ __forceinline__ int swz(int row, int g) {
    return row * 64 + (((g ^ (row >> 2)) & 15) << 2);
}

extern __shared__ float smem[];

__global__ void __launch_bounds__(256, 2)
attn_kernel(const float* __restrict__ Q, const float* __restrict__ K,
            const float* __restrict__ V) {
    int b  = blockIdx.y;
    int sp = blockIdx.z;
    int nq = g_qcnt[b];
    int nk = g_kcnt[b];
    int q0 = blockIdx.x * TQ;
    if (q0 >= nq) return;   // early exit before any barrier

    float* Qs = smem;            // 4096 floats
    float* Kt = smem + 4096;     // 4096 (transposed K)
    float* Vs = smem + 8192;     // 4096
    float* Ps = smem + 12288;    // 4096

    int tid = threadIdx.x;
    int tx = tid & 15;           // k / d micro-tile column group
    int ty = tid >> 4;           // q micro-tile row group

    // ---- load Q tile (gathered, pre-scaled by 1/sqrt(D)=0.125) ----
    {
        int g = tid & 15;
        int r = tid >> 4;
#pragma unroll
        for (int pass = 0; pass < 4; ++pass) {
            int row = r + pass * 16;
            int qi = q0 + row;
            float4 v = make_float4(0.f, 0.f, 0.f, 0.f);
            if (qi < nq) {
                int src = g_qlist[b][qi];
                v = *(const float4*)&Q[((size_t)b * LL + src) * DD + g * 4];
                v.x *= 0.125f; v.y *= 0.125f; v.z *= 0.125f; v.w *= 0.125f;
            }
            *(float4*)&Qs[swz(row, g)] = v;
        }
    }
    __syncthreads();

    // packed accumulators: acc2[i][0]=(d0,d1), acc2[i][1]=(d2,d3) at d=4tx..
    unsigned long long acc2[4][2];
    float rs[4];
#pragma unroll
    for (int i = 0; i < 4; ++i) {
        rs[i] = 0.f;
        acc2[i][0] = 0ull; acc2[i][1] = 0ull;
    }

    int ntiles = (nk + TK - 1) / TK;
    int half   = (ntiles + 1) >> 1;
    int tbeg   = sp * half;
    int tend   = (sp == 0) ? half : ntiles;

    for (int t = tbeg; t < tend; ++t) {
        int k0 = t * TK;

        // ---- load K (transposed into Kt) and V tiles (gathered) ----
        {
            int g = tid & 15;
            int r = tid >> 4;
#pragma unroll
            for (int pass = 0; pass < 4; ++pass) {
                int row = r + pass * 16;
                int ki = k0 + row;
                float4 kv = make_float4(0.f, 0.f, 0.f, 0.f);
                float4 vv = make_float4(0.f, 0.f, 0.f, 0.f);
                if (ki < nk) {
                    int src = g_klist[b][ki];
                    kv = *(const float4*)&K[((size_t)b * LL + src) * DD + g * 4];
                    vv = *(const float4*)&V[((size_t)b * LL + src) * DD + g * 4];
                }
                // transpose K: element (d = 4g+c, k = row)
                int rg = row >> 2, rl = row & 3;
                Kt[swz(4 * g + 0, rg) + rl] = kv.x;
                Kt[swz(4 * g + 1, rg) + rl] = kv.y;
                Kt[swz(4 * g + 2, rg) + rl] = kv.z;
                Kt[swz(4 * g + 3, rg) + rl] = kv.w;
                *(float4*)&Vs[swz(row, g)] = vv;
            }
        }
        __syncthreads();

        // ---- phase A: S = Qs @ Kt (packed over k pairs) ----
        unsigned long long s2[4][2];
#pragma unroll
        for (int i = 0; i < 4; ++i) { s2[i][0] = 0ull; s2[i][1] = 0ull; }

#pragma unroll
        for (int dg = 0; dg < 16; ++dg) {
            ulonglong2 kp[4];   // kp[c]: k values (4tx..4tx+3) at d=4dg+c
#pragma unroll
            for (int c = 0; c < 4; ++c)
                kp[c] = *(const ulonglong2*)&Kt[swz(4 * dg + c, tx)];
#pragma unroll
            for (int i = 0; i < 4; ++i) {
                float4 qv = *(const float4*)&Qs[swz(ty * 4 + i, dg)];
                unsigned long long qq;
                qq = pack2(qv.x, qv.x);
                ffma2(s2[i][0], qq, kp[0].x); ffma2(s2[i][1], qq, kp[0].y);
                qq = pack2(qv.y, qv.y);
                ffma2(s2[i][0], qq, kp[1].x); ffma2(s2[i][1], qq, kp[1].y);
                qq = pack2(qv.z, qv.z);
                ffma2(s2[i][0], qq, kp[2].x); ffma2(s2[i][1], qq, kp[2].y);
                qq = pack2(qv.w, qv.w);
                ffma2(s2[i][0], qq, kp[3].x); ffma2(s2[i][1], qq, kp[3].y);
            }
        }

        // exp, accumulate row sums, write P tile
        int kc = k0 + tx * 4;
#pragma unroll
        for (int i = 0; i < 4; ++i) {
            float s0, s1, s2v, s3;
            unpack2(s2[i][0], s0, s1);
            unpack2(s2[i][1], s2v, s3);
            float e0 = (kc + 0 < nk) ? __expf(s0)  : 0.0f;
            float e1 = (kc + 1 < nk) ? __expf(s1)  : 0.0f;
            float e2 = (kc + 2 < nk) ? __expf(s2v) : 0.0f;
            float e3 = (kc + 3 < nk) ? __expf(s3)  : 0.0f;
            rs[i] += e0 + e1 + e2 + e3;
            *(float4*)&Ps[swz(ty * 4 + i, tx)] = make_float4(e0, e1, e2, e3);
        }
        __syncthreads();

        // ---- phase B: O += P @ V (packed over d pairs) ----
#pragma unroll
        for (int kg = 0; kg < 16; ++kg) {
            ulonglong2 vp[4];   // vp[c]: d values (4tx..4tx+3) at k=4kg+c
#pragma unroll
            for (int c = 0; c < 4; ++c)
                vp[c] = *(const ulonglong2*)&Vs[swz(kg * 4 + c, tx)];
#pragma unroll
            for (int i = 0; i < 4; ++i) {
                float4 p = *(const float4*)&Ps[swz(ty * 4 + i, kg)];
                unsigned long long pp;
                pp = pack2(p.x, p.x);
                ffma2(acc2[i][0], pp, vp[0].x); ffma2(acc2[i][1], pp, vp[0].y);
                pp = pack2(p.y, p.y);
                ffma2(acc2[i][0], pp, vp[1].x); ffma2(acc2[i][1], pp, vp[1].y);
                pp = pack2(p.z, p.z);
                ffma2(acc2[i][0], pp, vp[2].x); ffma2(acc2[i][1], pp, vp[2].y);
                pp = pack2(p.w, p.w);
                ffma2(acc2[i][0], pp, vp[3].x); ffma2(acc2[i][1], pp, vp[3].y);
            }
        }
        __syncthreads();
    }

    // ---- reduce row sums across the 16 tx threads (deterministic order) ----
    float* RS = Kt;   // reuse: [qr][tx] partials, 64*16 floats
#pragma unroll
    for (int i = 0; i < 4; ++i)
        RS[(ty * 4 + i) * 16 + tx] = rs[i];
    __syncthreads();

    if (tid < 64) {
        int qi = q0 + tid;
        if (qi < nq) {
            float tsum = 0.f;
#pragma unroll
            for (int u = 0; u < 16; ++u) tsum += RS[tid * 16 + u];
            g_rspart[sp][b][qi] = tsum;   // clamp happens in combine
        }
    }

    // ---- write unnormalized O partials at compacted positions ----
#pragma unroll
    for (int i = 0; i < 4; ++i) {
        int qi = q0 + ty * 4 + i;
        if (qi < nq) {
            float a0, a1, a2, a3;
            unpack2(acc2[i][0], a0, a1);
            unpack2(acc2[i][1], a2, a3);
            *(float4*)&g_Opart[sp][b][qi][tx * 4] = make_float4(a0, a1, a2, a3);
        }
    }
}

// ---------------------------------------------------------------------------
// Kernel 3: combine splits, clamp rowsum, normalize, scatter (float4-wide).
// 256 threads = 16 q rows x 16 d-groups. Grid (LL/16, BB).
// ---------------------------------------------------------------------------
__global__ void combine_kernel(float* __restrict__ out) {
    int b  = blockIdx.y;
    int nq = g_qcnt[b];
    int qi = blockIdx.x * 16 + (threadIdx.x >> 4);
    int dg = threadIdx.x & 15;
    if (qi >= nq) return;
    float inv = 1.0f / fmaxf(g_rspart[0][b][qi] + g_rspart[1][b][qi], 1.0f);
    float4 o0 = *(const float4*)&g_Opart[0][b][qi][dg * 4];
    float4 o1 = *(const float4*)&g_Opart[1][b][qi][dg * 4];
    float4 o = make_float4((o0.x + o1.x) * inv, (o0.y + o1.y) * inv,
                           (o0.z + o1.z) * inv, (o0.w + o1.w) * inv);
    int src = g_qlist[b][qi];
    *(float4*)&out[((size_t)b * LL + src) * DD + dg * 4] = o;
}

// ---------------------------------------------------------------------------
extern "C" void kernel_launch(void* const* d_in, const int* in_sizes, int n_in,
                              void* d_out, int out_size) {
    const float* Q  = (const float*)d_in[0];
    const float* K  = (const float*)d_in[1];
    const float* V  = (const float*)d_in[2];
    const int*   qm = (const int*)d_in[3];
    const int*   km = (const int*)d_in[4];
    float* out = (float*)d_out;

    // 64 KB dynamic smem (> 48 KB default) — idempotent host-side config
    cudaFuncSetAttribute(attn_kernel,
                         cudaFuncAttributeMaxDynamicSharedMemorySize, 65536);

    // zero-fill output: invalid q rows stay exactly 0
    cudaMemsetAsync(out, 0, (size_t)out_size * sizeof(float));

    compact_kernel<<<BB, 256>>>(qm, km);

    dim3 grid(LL / TQ, BB, NSPLIT);   // 32 x 8 x 2; ~half exit early (q compaction)
    attn_kernel<<<grid, 256, 65536>>>(Q, K, V);

    dim3 cgrid(LL / 16, BB);
    combine_kernel<<<cgrid, 256>>>(out);
}